// round 8
// baseline (speedup 1.0000x reference)
#include <cuda_runtime.h>
#include <math.h>
#include <stdint.h>

#define BB 2
#define SS 2048
#define DD 1024
#define HH 16
#define MM (BB*SS)

// Scratch (allocation-free rule: __device__ globals)
__device__ float g_Q[(size_t)MM * DD];
__device__ float g_K[(size_t)MM * DD];
__device__ float g_V[(size_t)MM * DD];
__device__ float g_ctx[(size_t)MM * DD];

__device__ __forceinline__ uint32_t f2tf(float f) {
    uint32_t u; asm("cvt.rna.tf32.f32 %0, %1;" : "=r"(u) : "f"(f)); return u;
}
__device__ __forceinline__ void mma8(float* d, const uint32_t* a, const uint32_t* b) {
    asm volatile(
        "mma.sync.aligned.m16n8k8.row.col.f32.tf32.tf32.f32 "
        "{%0,%1,%2,%3}, {%4,%5,%6,%7}, {%8,%9}, {%0,%1,%2,%3};\n"
        : "+f"(d[0]), "+f"(d[1]), "+f"(d[2]), "+f"(d[3])
        : "r"(a[0]), "r"(a[1]), "r"(a[2]), "r"(a[3]), "r"(b[0]), "r"(b[1]));
}
__device__ __forceinline__ uint32_t smem_u32(const void* p) {
    uint32_t a;
    asm("{ .reg .u64 t; cvta.to.shared.u64 t, %1; cvt.u32.u64 %0, t; }"
        : "=r"(a) : "l"(p));
    return a;
}
__device__ __forceinline__ void cp16(uint32_t dst, const void* src) {
    asm volatile("cp.async.ca.shared.global [%0], [%1], 16;" :: "r"(dst), "l"(src));
}
#define CP_COMMIT() asm volatile("cp.async.commit_group;" ::: "memory")
#define CP_WAIT0()  asm volatile("cp.async.wait_group 0;" ::: "memory")
#define CP_WAIT1()  asm volatile("cp.async.wait_group 1;" ::: "memory")

// ===========================================================================
// GEMM: C = A @ W + bias (tf32 mma.sync), cp.async 3-stage pipeline.
// Block 128x128, BK=32, 256 threads = 8 warps as 2(M) x 4(N).
// Smem holds RAW fp32 (cp.async); cvt.rna at fragment load (same numerics).
// One __syncthreads per chunk; issue-after-barrier protects the reused stage.
// ===========================================================================
#define GPA 36
#define GPB 136
#define GA_SZ (128 * GPA)                 // 4608 words per A stage
#define GB_SZ (32 * GPB)                  // 4352 words per B stage
#define GEMM_SMEM ((3 * GA_SZ + 3 * GB_SZ) * 4)   // 107520 B

__global__ void __launch_bounds__(256) gemm_tc(
    const float* __restrict__ A0, const float* __restrict__ A1, const float* __restrict__ A2,
    const float* __restrict__ W0, const float* __restrict__ W1, const float* __restrict__ W2,
    const float* __restrict__ b0, const float* __restrict__ b1, const float* __restrict__ b2,
    float* __restrict__ C0, float* __restrict__ C1, float* __restrict__ C2)
{
    extern __shared__ float gsmf[];
    const uint32_t sbase = smem_u32(gsmf);
    const int z = blockIdx.z;
    const float* A = (z == 0) ? A0 : (z == 1) ? A1 : A2;
    const float* W = (z == 0) ? W0 : (z == 1) ? W1 : W2;
    const float* bias = (z == 0) ? b0 : (z == 1) ? b1 : b2;
    float* C = (z == 0) ? C0 : (z == 1) ? C1 : C2;

    const int tid  = threadIdx.x;
    const int lane = tid & 31, warp = tid >> 5;
    const int g = lane >> 2, tig = lane & 3;
    const int wm = warp >> 2, wn = warp & 3;
    const int row0 = blockIdx.y * 128, col0 = blockIdx.x * 128;

    auto issue_chunk = [&](int c2, int s) {
        const int k0 = c2 * 32;
        #pragma unroll
        for (int p = 0; p < 4; p++) {
            const int i = tid + 256 * p;
            const int r = i >> 3, ch = (i & 7) * 4;
            cp16(sbase + (uint32_t)(s * GA_SZ + r * GPA + ch) * 4,
                 A + (size_t)(row0 + r) * DD + k0 + ch);
        }
        #pragma unroll
        for (int p = 0; p < 4; p++) {
            const int i = tid + 256 * p;
            const int rb = i >> 5, ch = (i & 31) * 4;
            cp16(sbase + (uint32_t)(3 * GA_SZ + s * GB_SZ + rb * GPB + ch) * 4,
                 W + (size_t)(k0 + rb) * DD + col0 + ch);
        }
    };

    // prologue: stages 0 and 1 in flight
    issue_chunk(0, 0); CP_COMMIT();
    issue_chunk(1, 1); CP_COMMIT();

    float acc[4][4][4] = {};

    for (int c = 0; c < 32; c++) {
        CP_WAIT1();          // chunk c complete (c+1 may remain in flight)
        __syncthreads();     // visibility + stage (c+2)%3 reads (iter c-1) done

        if (c + 2 < 32) issue_chunk(c + 2, (c + 2) % 3);
        CP_COMMIT();         // (possibly empty group; keeps wait counts uniform)

        const float* Asf = gsmf + (c % 3) * GA_SZ;
        const float* Bsf = gsmf + 3 * GA_SZ + (c % 3) * GB_SZ;

        #pragma unroll
        for (int kk = 0; kk < 4; kk++) {
            const int kb = kk * 8;
            uint32_t af[4][4], bf[4][2];
            #pragma unroll
            for (int mt = 0; mt < 4; mt++) {
                const int r = wm * 64 + mt * 16 + g;
                af[mt][0] = f2tf(Asf[r * GPA + kb + tig]);
                af[mt][1] = f2tf(Asf[(r + 8) * GPA + kb + tig]);
                af[mt][2] = f2tf(Asf[r * GPA + kb + tig + 4]);
                af[mt][3] = f2tf(Asf[(r + 8) * GPA + kb + tig + 4]);
            }
            #pragma unroll
            for (int j = 0; j < 4; j++) {
                const int n = wn * 32 + j * 8 + g;
                bf[j][0] = f2tf(Bsf[(kb + tig) * GPB + n]);
                bf[j][1] = f2tf(Bsf[(kb + tig + 4) * GPB + n]);
            }
            #pragma unroll
            for (int mt = 0; mt < 4; mt++)
                #pragma unroll
                for (int j = 0; j < 4; j++)
                    mma8(acc[mt][j], af[mt], bf[j]);
        }
    }

    // epilogue
    #pragma unroll
    for (int mt = 0; mt < 4; mt++) {
        #pragma unroll
        for (int j = 0; j < 4; j++) {
            const int n = col0 + wn * 32 + j * 8 + 2 * tig;
            const float bb0 = bias[n], bb1 = bias[n + 1];
            const int r = row0 + wm * 64 + mt * 16 + g;
            *(float2*)&C[(size_t)r * DD + n] =
                make_float2(acc[mt][j][0] + bb0, acc[mt][j][1] + bb1);
            *(float2*)&C[(size_t)(r + 8) * DD + n] =
                make_float2(acc[mt][j][2] + bb0, acc[mt][j][3] + bb1);
        }
    }
}

// ===========================================================================
// Flash attention, tf32 mma.sync, cp.async 2-stage K/V pipeline.
// CTA = (128-row q-tile, b, h). 128 threads = 4 warps x 32 q-rows (2 m-tiles).
// K stored RAW [key][dk] stride 76 (bank = 12g+tig, conflict-free B-frags);
// V RAW [key][dk] stride 72 (bank = 8tig+g). cvt.rna at fragment load.
// No fill STS, ONE __syncthreads per key-tile.
// SMEM: K[2][64*76] + V[2][64*72] + Ps[128][72] = 112640 B (2 CTAs/SM).
// ===========================================================================
#define APK 72
#define KST 76
#define VST 72
#define KB_SZ (64 * KST)                  // 4864 words
#define VB_SZ (64 * VST)                  // 4608 words
#define PS_OFF (2 * KB_SZ + 2 * VB_SZ)    // 18944 words
#define ATTN_SMEM ((PS_OFF + 128 * APK) * 4)   // 112640 B
#define NT (SS / 64)

__global__ void __launch_bounds__(128) attn_tc()
{
    extern __shared__ float smf[];
    uint32_t* smem_u = (uint32_t*)smf;
    const uint32_t sbase = smem_u32(smf);

    const int tid  = threadIdx.x;
    const int lane = tid & 31, warp = tid >> 5;
    const int g = lane >> 2, tig = lane & 3;
    const int wr0 = warp * 32;
    const int qt = blockIdx.x;
    const int b  = blockIdx.y >> 4;
    const int h  = blockIdx.y & 15;

    const float* Qg = g_Q + (size_t)(b * SS + qt * 128) * DD + h * 64;
    const float* Kg = g_K + (size_t)(b * SS) * DD + h * 64;
    const float* Vg = g_V + (size_t)(b * SS) * DD + h * 64;

    auto issue_tile = [&](int t2, int stg) {
        const float* Kt = Kg + (size_t)(t2 * 64) * DD;
        const float* Vt = Vg + (size_t)(t2 * 64) * DD;
        #pragma unroll
        for (int p = 0; p < 8; p++) {
            const int i = tid + 128 * p;
            const int r = i >> 4, ch = (i & 15) * 4;
            cp16(sbase + (uint32_t)(stg * KB_SZ + r * KST + ch) * 4,
                 Kt + (size_t)r * DD + ch);
            cp16(sbase + (uint32_t)(2 * KB_SZ + stg * VB_SZ + r * VST + ch) * 4,
                 Vt + (size_t)r * DD + ch);
        }
    };

    // ---- prologue: tile 0 in flight while we stage Q ----
    issue_tile(0, 0); CP_COMMIT();

    uint32_t* Ps = smem_u + PS_OFF;
    float*   Qst = (float*)Ps;
    {
        const int r = tid >> 4, c = (tid & 15) * 4;
        #pragma unroll
        for (int i = 0; i < 16; i++) {
            float4 qv = *(const float4*)(Qg + (size_t)(r + 8 * i) * DD + c);
            qv.x *= 0.125f; qv.y *= 0.125f; qv.z *= 0.125f; qv.w *= 0.125f;
            *(float4*)&Qst[(r + 8 * i) * APK + c] = qv;
        }
    }
    __syncthreads();

    uint32_t qa[2][8][4];
    #pragma unroll
    for (int mt = 0; mt < 2; mt++) {
        const int r = wr0 + mt * 16 + g;
        #pragma unroll
        for (int k8 = 0; k8 < 8; k8++) {
            qa[mt][k8][0] = f2tf(Qst[r * APK + k8 * 8 + tig]);
            qa[mt][k8][1] = f2tf(Qst[(r + 8) * APK + k8 * 8 + tig]);
            qa[mt][k8][2] = f2tf(Qst[r * APK + k8 * 8 + tig + 4]);
            qa[mt][k8][3] = f2tf(Qst[(r + 8) * APK + k8 * 8 + tig + 4]);
        }
    }
    // (no barrier needed: Ps region is next touched only by this warp's P
    //  stores, which follow in program order)

    float of[2][8][4] = {};
    float mrow[2][2] = {{-1e30f, -1e30f}, {-1e30f, -1e30f}};
    float lrow[2][2] = {{0.f, 0.f}, {0.f, 0.f}};

    for (int kt = 0; kt < NT; kt++) {
        CP_WAIT0();          // tile kt landed
        __syncthreads();     // visibility; also: all warps done with buf[(kt+1)&1]

        if (kt + 1 < NT) { issue_tile(kt + 1, (kt + 1) & 1); CP_COMMIT(); }

        const float* KBf = smf + (kt & 1) * KB_SZ;
        const float* VBf = smf + 2 * KB_SZ + (kt & 1) * VB_SZ;

        // ---- S = Qs @ K^T : B-frags from raw K[key][dk], cvt at load ----
        float sf[2][8][4] = {};
        #pragma unroll
        for (int k8 = 0; k8 < 8; k8++) {
            const int kr = k8 * 8 + tig;
            uint32_t bf[8][2];
            #pragma unroll
            for (int j = 0; j < 8; j++) {
                const int n = j * 8 + g;
                bf[j][0] = f2tf(KBf[n * KST + kr]);
                bf[j][1] = f2tf(KBf[n * KST + kr + 4]);
            }
            #pragma unroll
            for (int mt = 0; mt < 2; mt++)
                #pragma unroll
                for (int j = 0; j < 8; j++)
                    mma8(sf[mt][j], qa[mt][k8], bf[j]);
        }

        // ---- online softmax ----
        #pragma unroll
        for (int mt = 0; mt < 2; mt++) {
            #pragma unroll
            for (int i = 0; i < 2; i++) {
                float mx = -1e30f;
                #pragma unroll
                for (int j = 0; j < 8; j++)
                    mx = fmaxf(mx, fmaxf(sf[mt][j][2 * i], sf[mt][j][2 * i + 1]));
                mx = fmaxf(mx, __shfl_xor_sync(0xffffffffu, mx, 1));
                mx = fmaxf(mx, __shfl_xor_sync(0xffffffffu, mx, 2));
                const float mn = fmaxf(mrow[mt][i], mx);
                const float corr = __expf(mrow[mt][i] - mn);
                mrow[mt][i] = mn;
                float rs = 0.f;
                #pragma unroll
                for (int j = 0; j < 8; j++) {
                    sf[mt][j][2 * i]     = __expf(sf[mt][j][2 * i] - mn);
                    sf[mt][j][2 * i + 1] = __expf(sf[mt][j][2 * i + 1] - mn);
                    rs += sf[mt][j][2 * i] + sf[mt][j][2 * i + 1];
                }
                rs += __shfl_xor_sync(0xffffffffu, rs, 1);
                rs += __shfl_xor_sync(0xffffffffu, rs, 2);
                lrow[mt][i] = lrow[mt][i] * corr + rs;
                #pragma unroll
                for (int j = 0; j < 8; j++) {
                    of[mt][j][2 * i]     *= corr;
                    of[mt][j][2 * i + 1] *= corr;
                }
            }
        }

        // ---- P -> Ps (tf32); warp-private rows -> warp sync only ----
        #pragma unroll
        for (int mt = 0; mt < 2; mt++) {
            const int r = wr0 + mt * 16 + g;
            #pragma unroll
            for (int j = 0; j < 8; j++) {
                *(uint2*)&Ps[r * APK + j * 8 + 2 * tig] =
                    make_uint2(f2tf(sf[mt][j][0]), f2tf(sf[mt][j][1]));
                *(uint2*)&Ps[(r + 8) * APK + j * 8 + 2 * tig] =
                    make_uint2(f2tf(sf[mt][j][2]), f2tf(sf[mt][j][3]));
            }
        }
        __syncwarp();

        // ---- O += P @ V : B-frags from raw V[key][dk], cvt at load ----
        #pragma unroll
        for (int k8 = 0; k8 < 8; k8++) {
            const int vr = k8 * 8 + tig;
            uint32_t pa[2][4];
            #pragma unroll
            for (int mt = 0; mt < 2; mt++) {
                const int r = wr0 + mt * 16 + g;
                pa[mt][0] = Ps[r * APK + k8 * 8 + tig];
                pa[mt][1] = Ps[(r + 8) * APK + k8 * 8 + tig];
                pa[mt][2] = Ps[r * APK + k8 * 8 + tig + 4];
                pa[mt][3] = Ps[(r + 8) * APK + k8 * 8 + tig + 4];
            }
            #pragma unroll
            for (int j = 0; j < 8; j++) {
                const int n = j * 8 + g;
                uint32_t bb[2];
                bb[0] = f2tf(VBf[vr * VST + n]);
                bb[1] = f2tf(VBf[(vr + 4) * VST + n]);
                #pragma unroll
                for (int mt = 0; mt < 2; mt++)
                    mma8(of[mt][j], pa[mt], bb);
            }
        }
    }

    // ---- normalize + write context ----
    #pragma unroll
    for (int mt = 0; mt < 2; mt++) {
        const float inv0 = 1.f / lrow[mt][0], inv1 = 1.f / lrow[mt][1];
        const size_t orow = (size_t)(b * SS + qt * 128 + wr0 + mt * 16 + g);
        #pragma unroll
        for (int j = 0; j < 8; j++) {
            const int n = h * 64 + j * 8 + 2 * tig;
            *(float2*)&g_ctx[orow * DD + n] =
                make_float2(of[mt][j][0] * inv0, of[mt][j][1] * inv0);
            *(float2*)&g_ctx[(orow + 8) * DD + n] =
                make_float2(of[mt][j][2] * inv1, of[mt][j][3] * inv1);
        }
    }
}

// ---------------------------------------------------------------------------
extern "C" void kernel_launch(void* const* d_in, const int* in_sizes, int n_in,
                              void* d_out, int out_size)
{
    (void)in_sizes; (void)n_in; (void)out_size;
    const float* q  = (const float*)d_in[0];
    const float* k  = (const float*)d_in[1];
    const float* v  = (const float*)d_in[2];
    const float* wq = (const float*)d_in[3];
    const float* bq = (const float*)d_in[4];
    const float* wk = (const float*)d_in[5];
    const float* bk = (const float*)d_in[6];
    const float* wv = (const float*)d_in[7];
    const float* bv = (const float*)d_in[8];
    const float* wo = (const float*)d_in[9];
    const float* bo = (const float*)d_in[10];
    float* out = (float*)d_out;

    float *gq, *gk, *gv, *gctx;
    cudaGetSymbolAddress((void**)&gq,   g_Q);
    cudaGetSymbolAddress((void**)&gk,   g_K);
    cudaGetSymbolAddress((void**)&gv,   g_V);
    cudaGetSymbolAddress((void**)&gctx, g_ctx);

    cudaFuncSetAttribute(gemm_tc, cudaFuncAttributeMaxDynamicSharedMemorySize, GEMM_SMEM);
    cudaFuncSetAttribute(attn_tc, cudaFuncAttributeMaxDynamicSharedMemorySize, ATTN_SMEM);

    // fused Q/K/V projections: one launch, grid.z = 3
    gemm_tc<<<dim3(DD / 128, MM / 128, 3), 256, GEMM_SMEM>>>(
        q, k, v, wq, wk, wv, bq, bk, bv, gq, gk, gv);

    attn_tc<<<dim3(SS / 128, BB * HH), 128, ATTN_SMEM>>>();

    // output projection
    gemm_tc<<<dim3(DD / 128, MM / 128, 1), 256, GEMM_SMEM>>>(
        gctx, gctx, gctx, wo, wo, wo, bo, bo, bo, out, out, out);
}

// round 9
// speedup vs baseline: 1.1408x; 1.1408x over previous
#include <cuda_runtime.h>
#include <math.h>
#include <stdint.h>

#define BB 2
#define SS 2048
#define DD 1024
#define HH 16
#define MM (BB*SS)

// Scratch (allocation-free rule: __device__ globals)
__device__ float g_Q[(size_t)MM * DD];
__device__ float g_K[(size_t)MM * DD];
__device__ float g_V[(size_t)MM * DD];
__device__ float g_ctx[(size_t)MM * DD];

__device__ __forceinline__ uint32_t f2tf(float f) {
    uint32_t u; asm("cvt.rna.tf32.f32 %0, %1;" : "=r"(u) : "f"(f)); return u;
}
__device__ __forceinline__ void mma8(float* d, const uint32_t* a, const uint32_t* b) {
    asm volatile(
        "mma.sync.aligned.m16n8k8.row.col.f32.tf32.tf32.f32 "
        "{%0,%1,%2,%3}, {%4,%5,%6,%7}, {%8,%9}, {%0,%1,%2,%3};\n"
        : "+f"(d[0]), "+f"(d[1]), "+f"(d[2]), "+f"(d[3])
        : "r"(a[0]), "r"(a[1]), "r"(a[2]), "r"(a[3]), "r"(b[0]), "r"(b[1]));
}
__device__ __forceinline__ uint32_t smem_u32(const void* p) {
    uint32_t a;
    asm("{ .reg .u64 t; cvta.to.shared.u64 t, %1; cvt.u32.u64 %0, t; }"
        : "=r"(a) : "l"(p));
    return a;
}
__device__ __forceinline__ void cp16(uint32_t dst, const void* src) {
    asm volatile("cp.async.ca.shared.global [%0], [%1], 16;" :: "r"(dst), "l"(src));
}
#define CP_COMMIT() asm volatile("cp.async.commit_group;" ::: "memory")
#define CP_WAIT0()  asm volatile("cp.async.wait_group 0;" ::: "memory")

// ===========================================================================
// GEMM: C = A @ W + bias (tf32 mma.sync).  R6 version (proven 183us QKV).
// Block 128x128, BK=32, 256 threads = 8 warps as 2(M) x 4(N).
// Ping-pong SMEM, store-side convert, register prefetch, 1 barrier/chunk.
// ===========================================================================
#define GPA 36
#define GPB 136
#define GA_SZ (128 * GPA)
#define GB_SZ (32 * GPB)
#define GEMM_SMEM ((2 * GA_SZ + 2 * GB_SZ) * 4)   // 71680 B

__global__ void __launch_bounds__(256) gemm_tc(
    const float* __restrict__ A0, const float* __restrict__ A1, const float* __restrict__ A2,
    const float* __restrict__ W0, const float* __restrict__ W1, const float* __restrict__ W2,
    const float* __restrict__ b0, const float* __restrict__ b1, const float* __restrict__ b2,
    float* __restrict__ C0, float* __restrict__ C1, float* __restrict__ C2)
{
    extern __shared__ uint32_t gsm[];
    const int z = blockIdx.z;
    const float* A = (z == 0) ? A0 : (z == 1) ? A1 : A2;
    const float* W = (z == 0) ? W0 : (z == 1) ? W1 : W2;
    const float* bias = (z == 0) ? b0 : (z == 1) ? b1 : b2;
    float* C = (z == 0) ? C0 : (z == 1) ? C1 : C2;

    const int tid  = threadIdx.x;
    const int lane = tid & 31, warp = tid >> 5;
    const int g = lane >> 2, tig = lane & 3;
    const int wm = warp >> 2, wn = warp & 3;
    const int row0 = blockIdx.y * 128, col0 = blockIdx.x * 128;

    const int rA = tid >> 3, cA = (tid & 7) * 4;
    const int rB = tid >> 5, cB = (tid & 31) * 4;
    const float* Ap = A + (size_t)(row0 + rA) * DD + cA;
    const float* Wp = W + (size_t)rB * DD + col0 + cB;

    float acc[4][4][4] = {};
    float4 av[4], wv[4];

    #pragma unroll
    for (int i = 0; i < 4; i++) av[i] = *(const float4*)(Ap + (size_t)(32 * i) * DD);
    #pragma unroll
    for (int i = 0; i < 4; i++) wv[i] = *(const float4*)(Wp + (size_t)(8 * i) * DD);
    {
        uint32_t* As = gsm;
        uint32_t* Bs = gsm + 2 * GA_SZ;
        #pragma unroll
        for (int i = 0; i < 4; i++)
            *(uint4*)&As[(rA + 32 * i) * GPA + cA] =
                make_uint4(f2tf(av[i].x), f2tf(av[i].y), f2tf(av[i].z), f2tf(av[i].w));
        #pragma unroll
        for (int i = 0; i < 4; i++)
            *(uint4*)&Bs[(rB + 8 * i) * GPB + cB] =
                make_uint4(f2tf(wv[i].x), f2tf(wv[i].y), f2tf(wv[i].z), f2tf(wv[i].w));
    }
    __syncthreads();

    for (int c = 0; c < 32; c++) {
        if (c + 1 < 32) {
            const int k0 = (c + 1) * 32;
            #pragma unroll
            for (int i = 0; i < 4; i++)
                av[i] = *(const float4*)(Ap + k0 + (size_t)(32 * i) * DD);
            #pragma unroll
            for (int i = 0; i < 4; i++)
                wv[i] = *(const float4*)(Wp + (size_t)(k0 + 8 * i) * DD);
        }

        const uint32_t* As = gsm + (c & 1) * GA_SZ;
        const uint32_t* Bs = gsm + 2 * GA_SZ + (c & 1) * GB_SZ;

        #pragma unroll
        for (int kk = 0; kk < 4; kk++) {
            const int kb = kk * 8;
            uint32_t af[4][4], bf[4][2];
            #pragma unroll
            for (int mt = 0; mt < 4; mt++) {
                const int r = wm * 64 + mt * 16 + g;
                af[mt][0] = As[r * GPA + kb + tig];
                af[mt][1] = As[(r + 8) * GPA + kb + tig];
                af[mt][2] = As[r * GPA + kb + tig + 4];
                af[mt][3] = As[(r + 8) * GPA + kb + tig + 4];
            }
            #pragma unroll
            for (int j = 0; j < 4; j++) {
                const int n = wn * 32 + j * 8 + g;
                bf[j][0] = Bs[(kb + tig) * GPB + n];
                bf[j][1] = Bs[(kb + tig + 4) * GPB + n];
            }
            #pragma unroll
            for (int mt = 0; mt < 4; mt++)
                #pragma unroll
                for (int j = 0; j < 4; j++)
                    mma8(acc[mt][j], af[mt], bf[j]);
        }

        if (c + 1 < 32) {
            uint32_t* Asn = gsm + ((c + 1) & 1) * GA_SZ;
            uint32_t* Bsn = gsm + 2 * GA_SZ + ((c + 1) & 1) * GB_SZ;
            #pragma unroll
            for (int i = 0; i < 4; i++)
                *(uint4*)&Asn[(rA + 32 * i) * GPA + cA] =
                    make_uint4(f2tf(av[i].x), f2tf(av[i].y), f2tf(av[i].z), f2tf(av[i].w));
            #pragma unroll
            for (int i = 0; i < 4; i++)
                *(uint4*)&Bsn[(rB + 8 * i) * GPB + cB] =
                    make_uint4(f2tf(wv[i].x), f2tf(wv[i].y), f2tf(wv[i].z), f2tf(wv[i].w));
            __syncthreads();
        }
    }

    #pragma unroll
    for (int mt = 0; mt < 4; mt++) {
        #pragma unroll
        for (int j = 0; j < 4; j++) {
            const int n = col0 + wn * 32 + j * 8 + 2 * tig;
            const float bb0 = bias[n], bb1 = bias[n + 1];
            const int r = row0 + wm * 64 + mt * 16 + g;
            *(float2*)&C[(size_t)r * DD + n] =
                make_float2(acc[mt][j][0] + bb0, acc[mt][j][1] + bb1);
            *(float2*)&C[(size_t)(r + 8) * DD + n] =
                make_float2(acc[mt][j][2] + bb0, acc[mt][j][3] + bb1);
        }
    }
}

// ===========================================================================
// Flash attention, tf32 mma.sync, cp.async 2-stage K/V pipeline.
// R8 version (proven ~277us). CTA = (128-row q-tile, b, h), 128 threads.
// K raw [key][dk] stride 76; V raw stride 72; cvt at fragment load.
// ONE __syncthreads per key-tile.
// ===========================================================================
#define APK 72
#define KST 76
#define VST 72
#define KB_SZ (64 * KST)
#define VB_SZ (64 * VST)
#define PS_OFF (2 * KB_SZ + 2 * VB_SZ)
#define ATTN_SMEM ((PS_OFF + 128 * APK) * 4)   // 112640 B
#define NT (SS / 64)

__global__ void __launch_bounds__(128) attn_tc()
{
    extern __shared__ float smf[];
    uint32_t* smem_u = (uint32_t*)smf;
    const uint32_t sbase = smem_u32(smf);

    const int tid  = threadIdx.x;
    const int lane = tid & 31, warp = tid >> 5;
    const int g = lane >> 2, tig = lane & 3;
    const int wr0 = warp * 32;
    const int qt = blockIdx.x;
    const int b  = blockIdx.y >> 4;
    const int h  = blockIdx.y & 15;

    const float* Qg = g_Q + (size_t)(b * SS + qt * 128) * DD + h * 64;
    const float* Kg = g_K + (size_t)(b * SS) * DD + h * 64;
    const float* Vg = g_V + (size_t)(b * SS) * DD + h * 64;

    auto issue_tile = [&](int t2, int stg) {
        const float* Kt = Kg + (size_t)(t2 * 64) * DD;
        const float* Vt = Vg + (size_t)(t2 * 64) * DD;
        #pragma unroll
        for (int p = 0; p < 8; p++) {
            const int i = tid + 128 * p;
            const int r = i >> 4, ch = (i & 15) * 4;
            cp16(sbase + (uint32_t)(stg * KB_SZ + r * KST + ch) * 4,
                 Kt + (size_t)r * DD + ch);
            cp16(sbase + (uint32_t)(2 * KB_SZ + stg * VB_SZ + r * VST + ch) * 4,
                 Vt + (size_t)r * DD + ch);
        }
    };

    issue_tile(0, 0); CP_COMMIT();

    uint32_t* Ps = smem_u + PS_OFF;
    float*   Qst = (float*)Ps;
    {
        const int r = tid >> 4, c = (tid & 15) * 4;
        #pragma unroll
        for (int i = 0; i < 16; i++) {
            float4 qv = *(const float4*)(Qg + (size_t)(r + 8 * i) * DD + c);
            qv.x *= 0.125f; qv.y *= 0.125f; qv.z *= 0.125f; qv.w *= 0.125f;
            *(float4*)&Qst[(r + 8 * i) * APK + c] = qv;
        }
    }
    __syncthreads();

    uint32_t qa[2][8][4];
    #pragma unroll
    for (int mt = 0; mt < 2; mt++) {
        const int r = wr0 + mt * 16 + g;
        #pragma unroll
        for (int k8 = 0; k8 < 8; k8++) {
            qa[mt][k8][0] = f2tf(Qst[r * APK + k8 * 8 + tig]);
            qa[mt][k8][1] = f2tf(Qst[(r + 8) * APK + k8 * 8 + tig]);
            qa[mt][k8][2] = f2tf(Qst[r * APK + k8 * 8 + tig + 4]);
            qa[mt][k8][3] = f2tf(Qst[(r + 8) * APK + k8 * 8 + tig + 4]);
        }
    }

    float of[2][8][4] = {};
    float mrow[2][2] = {{-1e30f, -1e30f}, {-1e30f, -1e30f}};
    float lrow[2][2] = {{0.f, 0.f}, {0.f, 0.f}};

    for (int kt = 0; kt < NT; kt++) {
        CP_WAIT0();
        __syncthreads();

        if (kt + 1 < NT) { issue_tile(kt + 1, (kt + 1) & 1); CP_COMMIT(); }

        const float* KBf = smf + (kt & 1) * KB_SZ;
        const float* VBf = smf + 2 * KB_SZ + (kt & 1) * VB_SZ;

        float sf[2][8][4] = {};
        #pragma unroll
        for (int k8 = 0; k8 < 8; k8++) {
            const int kr = k8 * 8 + tig;
            uint32_t bf[8][2];
            #pragma unroll
            for (int j = 0; j < 8; j++) {
                const int n = j * 8 + g;
                bf[j][0] = f2tf(KBf[n * KST + kr]);
                bf[j][1] = f2tf(KBf[n * KST + kr + 4]);
            }
            #pragma unroll
            for (int mt = 0; mt < 2; mt++)
                #pragma unroll
                for (int j = 0; j < 8; j++)
                    mma8(sf[mt][j], qa[mt][k8], bf[j]);
        }

        #pragma unroll
        for (int mt = 0; mt < 2; mt++) {
            #pragma unroll
            for (int i = 0; i < 2; i++) {
                float mx = -1e30f;
                #pragma unroll
                for (int j = 0; j < 8; j++)
                    mx = fmaxf(mx, fmaxf(sf[mt][j][2 * i], sf[mt][j][2 * i + 1]));
                mx = fmaxf(mx, __shfl_xor_sync(0xffffffffu, mx, 1));
                mx = fmaxf(mx, __shfl_xor_sync(0xffffffffu, mx, 2));
                const float mn = fmaxf(mrow[mt][i], mx);
                const float corr = __expf(mrow[mt][i] - mn);
                mrow[mt][i] = mn;
                float rs = 0.f;
                #pragma unroll
                for (int j = 0; j < 8; j++) {
                    sf[mt][j][2 * i]     = __expf(sf[mt][j][2 * i] - mn);
                    sf[mt][j][2 * i + 1] = __expf(sf[mt][j][2 * i + 1] - mn);
                    rs += sf[mt][j][2 * i] + sf[mt][j][2 * i + 1];
                }
                rs += __shfl_xor_sync(0xffffffffu, rs, 1);
                rs += __shfl_xor_sync(0xffffffffu, rs, 2);
                lrow[mt][i] = lrow[mt][i] * corr + rs;
                #pragma unroll
                for (int j = 0; j < 8; j++) {
                    of[mt][j][2 * i]     *= corr;
                    of[mt][j][2 * i + 1] *= corr;
                }
            }
        }

        #pragma unroll
        for (int mt = 0; mt < 2; mt++) {
            const int r = wr0 + mt * 16 + g;
            #pragma unroll
            for (int j = 0; j < 8; j++) {
                *(uint2*)&Ps[r * APK + j * 8 + 2 * tig] =
                    make_uint2(f2tf(sf[mt][j][0]), f2tf(sf[mt][j][1]));
                *(uint2*)&Ps[(r + 8) * APK + j * 8 + 2 * tig] =
                    make_uint2(f2tf(sf[mt][j][2]), f2tf(sf[mt][j][3]));
            }
        }
        __syncwarp();

        #pragma unroll
        for (int k8 = 0; k8 < 8; k8++) {
            const int vr = k8 * 8 + tig;
            uint32_t pa[2][4];
            #pragma unroll
            for (int mt = 0; mt < 2; mt++) {
                const int r = wr0 + mt * 16 + g;
                pa[mt][0] = Ps[r * APK + k8 * 8 + tig];
                pa[mt][1] = Ps[(r + 8) * APK + k8 * 8 + tig];
                pa[mt][2] = Ps[r * APK + k8 * 8 + tig + 4];
                pa[mt][3] = Ps[(r + 8) * APK + k8 * 8 + tig + 4];
            }
            #pragma unroll
            for (int j = 0; j < 8; j++) {
                const int n = j * 8 + g;
                uint32_t bb[2];
                bb[0] = f2tf(VBf[vr * VST + n]);
                bb[1] = f2tf(VBf[(vr + 4) * VST + n]);
                #pragma unroll
                for (int mt = 0; mt < 2; mt++)
                    mma8(of[mt][j], pa[mt], bb);
            }
        }
    }

    #pragma unroll
    for (int mt = 0; mt < 2; mt++) {
        const float inv0 = 1.f / lrow[mt][0], inv1 = 1.f / lrow[mt][1];
        const size_t orow = (size_t)(b * SS + qt * 128 + wr0 + mt * 16 + g);
        #pragma unroll
        for (int j = 0; j < 8; j++) {
            const int n = h * 64 + j * 8 + 2 * tig;
            *(float2*)&g_ctx[orow * DD + n] =
                make_float2(of[mt][j][0] * inv0, of[mt][j][1] * inv0);
            *(float2*)&g_ctx[(orow + 8) * DD + n] =
                make_float2(of[mt][j][2] * inv1, of[mt][j][3] * inv1);
        }
    }
}

// ---------------------------------------------------------------------------
extern "C" void kernel_launch(void* const* d_in, const int* in_sizes, int n_in,
                              void* d_out, int out_size)
{
    (void)in_sizes; (void)n_in; (void)out_size;
    const float* q  = (const float*)d_in[0];
    const float* k  = (const float*)d_in[1];
    const float* v  = (const float*)d_in[2];
    const float* wq = (const float*)d_in[3];
    const float* bq = (const float*)d_in[4];
    const float* wk = (const float*)d_in[5];
    const float* bk = (const float*)d_in[6];
    const float* wv = (const float*)d_in[7];
    const float* bv = (const float*)d_in[8];
    const float* wo = (const float*)d_in[9];
    const float* bo = (const float*)d_in[10];
    float* out = (float*)d_out;

    float *gq, *gk, *gv, *gctx;
    cudaGetSymbolAddress((void**)&gq,   g_Q);
    cudaGetSymbolAddress((void**)&gk,   g_K);
    cudaGetSymbolAddress((void**)&gv,   g_V);
    cudaGetSymbolAddress((void**)&gctx, g_ctx);

    cudaFuncSetAttribute(gemm_tc, cudaFuncAttributeMaxDynamicSharedMemorySize, GEMM_SMEM);
    cudaFuncSetAttribute(attn_tc, cudaFuncAttributeMaxDynamicSharedMemorySize, ATTN_SMEM);

    // fused Q/K/V projections: one launch, grid.z = 3
    gemm_tc<<<dim3(DD / 128, MM / 128, 3), 256, GEMM_SMEM>>>(
        q, k, v, wq, wk, wv, bq, bk, bv, gq, gk, gv);

    attn_tc<<<dim3(SS / 128, BB * HH), 128, ATTN_SMEM>>>();

    // output projection
    gemm_tc<<<dim3(DD / 128, MM / 128, 1), 256, GEMM_SMEM>>>(
        gctx, gctx, gctx, wo, wo, wo, bo, bo, bo, out, out, out);
}

// round 10
// speedup vs baseline: 1.1864x; 1.0399x over previous
#include <cuda_runtime.h>
#include <math.h>
#include <stdint.h>

#define BB 2
#define SS 2048
#define DD 1024
#define HH 16
#define MM (BB*SS)

// Scratch (allocation-free rule: __device__ globals)
__device__ float g_Q[(size_t)MM * DD];
__device__ float g_K[(size_t)MM * DD];
__device__ float g_V[(size_t)MM * DD];
__device__ float g_ctx[(size_t)MM * DD];

__device__ __forceinline__ uint32_t f2tf(float f) {
    uint32_t u; asm("cvt.rna.tf32.f32 %0, %1;" : "=r"(u) : "f"(f)); return u;
}
__device__ __forceinline__ void mma8(float* d, const uint32_t* a, const uint32_t* b) {
    asm volatile(
        "mma.sync.aligned.m16n8k8.row.col.f32.tf32.tf32.f32 "
        "{%0,%1,%2,%3}, {%4,%5,%6,%7}, {%8,%9}, {%0,%1,%2,%3};\n"
        : "+f"(d[0]), "+f"(d[1]), "+f"(d[2]), "+f"(d[3])
        : "r"(a[0]), "r"(a[1]), "r"(a[2]), "r"(a[3]), "r"(b[0]), "r"(b[1]));
}
__device__ __forceinline__ uint32_t smem_u32(const void* p) {
    uint32_t a;
    asm("{ .reg .u64 t; cvta.to.shared.u64 t, %1; cvt.u32.u64 %0, t; }"
        : "=r"(a) : "l"(p));
    return a;
}
__device__ __forceinline__ void cp16(uint32_t dst, const void* src) {
    asm volatile("cp.async.ca.shared.global [%0], [%1], 16;" :: "r"(dst), "l"(src));
}
#define CP_COMMIT() asm volatile("cp.async.commit_group;" ::: "memory")
#define CP_WAIT0()  asm volatile("cp.async.wait_group 0;" ::: "memory")

// ===========================================================================
// GEMM: C = A @ W + bias (tf32 mma.sync).  Proven version (183us QKV).
// Block 128x128, BK=32, 256 threads = 8 warps as 2(M) x 4(N).
// Ping-pong SMEM, store-side convert, register prefetch, 1 barrier/chunk.
// ===========================================================================
#define GPA 36
#define GPB 136
#define GA_SZ (128 * GPA)
#define GB_SZ (32 * GPB)
#define GEMM_SMEM ((2 * GA_SZ + 2 * GB_SZ) * 4)   // 71680 B

__global__ void __launch_bounds__(256) gemm_tc(
    const float* __restrict__ A0, const float* __restrict__ A1, const float* __restrict__ A2,
    const float* __restrict__ W0, const float* __restrict__ W1, const float* __restrict__ W2,
    const float* __restrict__ b0, const float* __restrict__ b1, const float* __restrict__ b2,
    float* __restrict__ C0, float* __restrict__ C1, float* __restrict__ C2)
{
    extern __shared__ uint32_t gsm[];
    const int z = blockIdx.z;
    const float* A = (z == 0) ? A0 : (z == 1) ? A1 : A2;
    const float* W = (z == 0) ? W0 : (z == 1) ? W1 : W2;
    const float* bias = (z == 0) ? b0 : (z == 1) ? b1 : b2;
    float* C = (z == 0) ? C0 : (z == 1) ? C1 : C2;

    const int tid  = threadIdx.x;
    const int lane = tid & 31, warp = tid >> 5;
    const int g = lane >> 2, tig = lane & 3;
    const int wm = warp >> 2, wn = warp & 3;
    const int row0 = blockIdx.y * 128, col0 = blockIdx.x * 128;

    const int rA = tid >> 3, cA = (tid & 7) * 4;
    const int rB = tid >> 5, cB = (tid & 31) * 4;
    const float* Ap = A + (size_t)(row0 + rA) * DD + cA;
    const float* Wp = W + (size_t)rB * DD + col0 + cB;

    float acc[4][4][4] = {};
    float4 av[4], wv[4];

    #pragma unroll
    for (int i = 0; i < 4; i++) av[i] = *(const float4*)(Ap + (size_t)(32 * i) * DD);
    #pragma unroll
    for (int i = 0; i < 4; i++) wv[i] = *(const float4*)(Wp + (size_t)(8 * i) * DD);
    {
        uint32_t* As = gsm;
        uint32_t* Bs = gsm + 2 * GA_SZ;
        #pragma unroll
        for (int i = 0; i < 4; i++)
            *(uint4*)&As[(rA + 32 * i) * GPA + cA] =
                make_uint4(f2tf(av[i].x), f2tf(av[i].y), f2tf(av[i].z), f2tf(av[i].w));
        #pragma unroll
        for (int i = 0; i < 4; i++)
            *(uint4*)&Bs[(rB + 8 * i) * GPB + cB] =
                make_uint4(f2tf(wv[i].x), f2tf(wv[i].y), f2tf(wv[i].z), f2tf(wv[i].w));
    }
    __syncthreads();

    for (int c = 0; c < 32; c++) {
        if (c + 1 < 32) {
            const int k0 = (c + 1) * 32;
            #pragma unroll
            for (int i = 0; i < 4; i++)
                av[i] = *(const float4*)(Ap + k0 + (size_t)(32 * i) * DD);
            #pragma unroll
            for (int i = 0; i < 4; i++)
                wv[i] = *(const float4*)(Wp + (size_t)(k0 + 8 * i) * DD);
        }

        const uint32_t* As = gsm + (c & 1) * GA_SZ;
        const uint32_t* Bs = gsm + 2 * GA_SZ + (c & 1) * GB_SZ;

        #pragma unroll
        for (int kk = 0; kk < 4; kk++) {
            const int kb = kk * 8;
            uint32_t af[4][4], bf[4][2];
            #pragma unroll
            for (int mt = 0; mt < 4; mt++) {
                const int r = wm * 64 + mt * 16 + g;
                af[mt][0] = As[r * GPA + kb + tig];
                af[mt][1] = As[(r + 8) * GPA + kb + tig];
                af[mt][2] = As[r * GPA + kb + tig + 4];
                af[mt][3] = As[(r + 8) * GPA + kb + tig + 4];
            }
            #pragma unroll
            for (int j = 0; j < 4; j++) {
                const int n = wn * 32 + j * 8 + g;
                bf[j][0] = Bs[(kb + tig) * GPB + n];
                bf[j][1] = Bs[(kb + tig + 4) * GPB + n];
            }
            #pragma unroll
            for (int mt = 0; mt < 4; mt++)
                #pragma unroll
                for (int j = 0; j < 4; j++)
                    mma8(acc[mt][j], af[mt], bf[j]);
        }

        if (c + 1 < 32) {
            uint32_t* Asn = gsm + ((c + 1) & 1) * GA_SZ;
            uint32_t* Bsn = gsm + 2 * GA_SZ + ((c + 1) & 1) * GB_SZ;
            #pragma unroll
            for (int i = 0; i < 4; i++)
                *(uint4*)&Asn[(rA + 32 * i) * GPA + cA] =
                    make_uint4(f2tf(av[i].x), f2tf(av[i].y), f2tf(av[i].z), f2tf(av[i].w));
            #pragma unroll
            for (int i = 0; i < 4; i++)
                *(uint4*)&Bsn[(rB + 8 * i) * GPB + cB] =
                    make_uint4(f2tf(wv[i].x), f2tf(wv[i].y), f2tf(wv[i].z), f2tf(wv[i].w));
            __syncthreads();
        }
    }

    #pragma unroll
    for (int mt = 0; mt < 4; mt++) {
        #pragma unroll
        for (int j = 0; j < 4; j++) {
            const int n = col0 + wn * 32 + j * 8 + 2 * tig;
            const float bb0 = bias[n], bb1 = bias[n + 1];
            const int r = row0 + wm * 64 + mt * 16 + g;
            *(float2*)&C[(size_t)r * DD + n] =
                make_float2(acc[mt][j][0] + bb0, acc[mt][j][1] + bb1);
            *(float2*)&C[(size_t)(r + 8) * DD + n] =
                make_float2(acc[mt][j][2] + bb0, acc[mt][j][3] + bb1);
        }
    }
}

// ===========================================================================
// Flash attention, tf32 mma.sync, cp.async 2-stage K/V pipeline.
// CTA = (256-row q-tile, b, h). 256 threads = 8 warps x 32 q-rows (2 m-tiles).
// Per-warp structure identical to the proven R8 kernel; doubling rows served
// per K/V tile pass halves fragment-LDS bytes per output.
// K raw [key][dk] stride 76; V raw stride 72; cvt at fragment load.
// SMEM: K[2][64*76] + V[2][64*72] + Ps[256][72] = 149504 B (1 CTA/SM, 8 warps)
// ===========================================================================
#define APK 72
#define KST 76
#define VST 72
#define KB_SZ (64 * KST)
#define VB_SZ (64 * VST)
#define PS_OFF (2 * KB_SZ + 2 * VB_SZ)
#define QT_ROWS 256
#define ATTN_SMEM ((PS_OFF + QT_ROWS * APK) * 4)   // 149504 B
#define NT (SS / 64)

__global__ void __launch_bounds__(256) attn_tc()
{
    extern __shared__ float smf[];
    uint32_t* smem_u = (uint32_t*)smf;
    const uint32_t sbase = smem_u32(smf);

    const int tid  = threadIdx.x;
    const int lane = tid & 31, warp = tid >> 5;
    const int g = lane >> 2, tig = lane & 3;
    const int wr0 = warp * 32;             // warp's first q-row (0..224)
    const int qt = blockIdx.x;
    const int b  = blockIdx.y >> 4;
    const int h  = blockIdx.y & 15;

    const float* Qg = g_Q + (size_t)(b * SS + qt * QT_ROWS) * DD + h * 64;
    const float* Kg = g_K + (size_t)(b * SS) * DD + h * 64;
    const float* Vg = g_V + (size_t)(b * SS) * DD + h * 64;

    auto issue_tile = [&](int t2, int stg) {
        const float* Kt = Kg + (size_t)(t2 * 64) * DD;
        const float* Vt = Vg + (size_t)(t2 * 64) * DD;
        #pragma unroll
        for (int p = 0; p < 4; p++) {
            const int i = tid + 256 * p;
            const int r = i >> 4, ch = (i & 15) * 4;
            cp16(sbase + (uint32_t)(stg * KB_SZ + r * KST + ch) * 4,
                 Kt + (size_t)r * DD + ch);
            cp16(sbase + (uint32_t)(2 * KB_SZ + stg * VB_SZ + r * VST + ch) * 4,
                 Vt + (size_t)r * DD + ch);
        }
    };

    issue_tile(0, 0); CP_COMMIT();

    uint32_t* Ps = smem_u + PS_OFF;
    float*   Qst = (float*)Ps;
    {
        const int r = tid >> 4, c = (tid & 15) * 4;
        #pragma unroll
        for (int i = 0; i < 16; i++) {
            float4 qv = *(const float4*)(Qg + (size_t)(r + 16 * i) * DD + c);
            qv.x *= 0.125f; qv.y *= 0.125f; qv.z *= 0.125f; qv.w *= 0.125f;
            *(float4*)&Qst[(r + 16 * i) * APK + c] = qv;
        }
    }
    __syncthreads();

    uint32_t qa[2][8][4];
    #pragma unroll
    for (int mt = 0; mt < 2; mt++) {
        const int r = wr0 + mt * 16 + g;
        #pragma unroll
        for (int k8 = 0; k8 < 8; k8++) {
            qa[mt][k8][0] = f2tf(Qst[r * APK + k8 * 8 + tig]);
            qa[mt][k8][1] = f2tf(Qst[(r + 8) * APK + k8 * 8 + tig]);
            qa[mt][k8][2] = f2tf(Qst[r * APK + k8 * 8 + tig + 4]);
            qa[mt][k8][3] = f2tf(Qst[(r + 8) * APK + k8 * 8 + tig + 4]);
        }
    }
    // (no barrier needed: each Ps row is next touched only by the warp that
    //  owns it, in program order)

    float of[2][8][4] = {};
    float mrow[2][2] = {{-1e30f, -1e30f}, {-1e30f, -1e30f}};
    float lrow[2][2] = {{0.f, 0.f}, {0.f, 0.f}};

    for (int kt = 0; kt < NT; kt++) {
        CP_WAIT0();
        __syncthreads();

        if (kt + 1 < NT) { issue_tile(kt + 1, (kt + 1) & 1); CP_COMMIT(); }

        const float* KBf = smf + (kt & 1) * KB_SZ;
        const float* VBf = smf + 2 * KB_SZ + (kt & 1) * VB_SZ;

        // ---- S = Qs @ K^T ----
        float sf[2][8][4] = {};
        #pragma unroll
        for (int k8 = 0; k8 < 8; k8++) {
            const int kr = k8 * 8 + tig;
            uint32_t bf[8][2];
            #pragma unroll
            for (int j = 0; j < 8; j++) {
                const int n = j * 8 + g;
                bf[j][0] = f2tf(KBf[n * KST + kr]);
                bf[j][1] = f2tf(KBf[n * KST + kr + 4]);
            }
            #pragma unroll
            for (int mt = 0; mt < 2; mt++)
                #pragma unroll
                for (int j = 0; j < 8; j++)
                    mma8(sf[mt][j], qa[mt][k8], bf[j]);
        }

        // ---- online softmax ----
        #pragma unroll
        for (int mt = 0; mt < 2; mt++) {
            #pragma unroll
            for (int i = 0; i < 2; i++) {
                float mx = -1e30f;
                #pragma unroll
                for (int j = 0; j < 8; j++)
                    mx = fmaxf(mx, fmaxf(sf[mt][j][2 * i], sf[mt][j][2 * i + 1]));
                mx = fmaxf(mx, __shfl_xor_sync(0xffffffffu, mx, 1));
                mx = fmaxf(mx, __shfl_xor_sync(0xffffffffu, mx, 2));
                const float mn = fmaxf(mrow[mt][i], mx);
                const float corr = __expf(mrow[mt][i] - mn);
                mrow[mt][i] = mn;
                float rs = 0.f;
                #pragma unroll
                for (int j = 0; j < 8; j++) {
                    sf[mt][j][2 * i]     = __expf(sf[mt][j][2 * i] - mn);
                    sf[mt][j][2 * i + 1] = __expf(sf[mt][j][2 * i + 1] - mn);
                    rs += sf[mt][j][2 * i] + sf[mt][j][2 * i + 1];
                }
                rs += __shfl_xor_sync(0xffffffffu, rs, 1);
                rs += __shfl_xor_sync(0xffffffffu, rs, 2);
                lrow[mt][i] = lrow[mt][i] * corr + rs;
                #pragma unroll
                for (int j = 0; j < 8; j++) {
                    of[mt][j][2 * i]     *= corr;
                    of[mt][j][2 * i + 1] *= corr;
                }
            }
        }

        // ---- P -> Ps (tf32); warp-private rows -> warp sync only ----
        #pragma unroll
        for (int mt = 0; mt < 2; mt++) {
            const int r = wr0 + mt * 16 + g;
            #pragma unroll
            for (int j = 0; j < 8; j++) {
                *(uint2*)&Ps[r * APK + j * 8 + 2 * tig] =
                    make_uint2(f2tf(sf[mt][j][0]), f2tf(sf[mt][j][1]));
                *(uint2*)&Ps[(r + 8) * APK + j * 8 + 2 * tig] =
                    make_uint2(f2tf(sf[mt][j][2]), f2tf(sf[mt][j][3]));
            }
        }
        __syncwarp();

        // ---- O += P @ V ----
        #pragma unroll
        for (int k8 = 0; k8 < 8; k8++) {
            const int vr = k8 * 8 + tig;
            uint32_t pa[2][4];
            #pragma unroll
            for (int mt = 0; mt < 2; mt++) {
                const int r = wr0 + mt * 16 + g;
                pa[mt][0] = Ps[r * APK + k8 * 8 + tig];
                pa[mt][1] = Ps[(r + 8) * APK + k8 * 8 + tig];
                pa[mt][2] = Ps[r * APK + k8 * 8 + tig + 4];
                pa[mt][3] = Ps[(r + 8) * APK + k8 * 8 + tig + 4];
            }
            #pragma unroll
            for (int j = 0; j < 8; j++) {
                const int n = j * 8 + g;
                uint32_t bb[2];
                bb[0] = f2tf(VBf[vr * VST + n]);
                bb[1] = f2tf(VBf[(vr + 4) * VST + n]);
                #pragma unroll
                for (int mt = 0; mt < 2; mt++)
                    mma8(of[mt][j], pa[mt], bb);
            }
        }
    }

    // ---- normalize + write context ----
    #pragma unroll
    for (int mt = 0; mt < 2; mt++) {
        const float inv0 = 1.f / lrow[mt][0], inv1 = 1.f / lrow[mt][1];
        const size_t orow = (size_t)(b * SS + qt * QT_ROWS + wr0 + mt * 16 + g);
        #pragma unroll
        for (int j = 0; j < 8; j++) {
            const int n = h * 64 + j * 8 + 2 * tig;
            *(float2*)&g_ctx[orow * DD + n] =
                make_float2(of[mt][j][0] * inv0, of[mt][j][1] * inv0);
            *(float2*)&g_ctx[(orow + 8) * DD + n] =
                make_float2(of[mt][j][2] * inv1, of[mt][j][3] * inv1);
        }
    }
}

// ---------------------------------------------------------------------------
extern "C" void kernel_launch(void* const* d_in, const int* in_sizes, int n_in,
                              void* d_out, int out_size)
{
    (void)in_sizes; (void)n_in; (void)out_size;
    const float* q  = (const float*)d_in[0];
    const float* k  = (const float*)d_in[1];
    const float* v  = (const float*)d_in[2];
    const float* wq = (const float*)d_in[3];
    const float* bq = (const float*)d_in[4];
    const float* wk = (const float*)d_in[5];
    const float* bk = (const float*)d_in[6];
    const float* wv = (const float*)d_in[7];
    const float* bv = (const float*)d_in[8];
    const float* wo = (const float*)d_in[9];
    const float* bo = (const float*)d_in[10];
    float* out = (float*)d_out;

    float *gq, *gk, *gv, *gctx;
    cudaGetSymbolAddress((void**)&gq,   g_Q);
    cudaGetSymbolAddress((void**)&gk,   g_K);
    cudaGetSymbolAddress((void**)&gv,   g_V);
    cudaGetSymbolAddress((void**)&gctx, g_ctx);

    cudaFuncSetAttribute(gemm_tc, cudaFuncAttributeMaxDynamicSharedMemorySize, GEMM_SMEM);
    cudaFuncSetAttribute(attn_tc, cudaFuncAttributeMaxDynamicSharedMemorySize, ATTN_SMEM);

    // fused Q/K/V projections: one launch, grid.z = 3
    gemm_tc<<<dim3(DD / 128, MM / 128, 3), 256, GEMM_SMEM>>>(
        q, k, v, wq, wk, wv, bq, bk, bv, gq, gk, gv);

    attn_tc<<<dim3(SS / QT_ROWS, BB * HH), 256, ATTN_SMEM>>>();

    // output projection
    gemm_tc<<<dim3(DD / 128, MM / 128, 1), 256, GEMM_SMEM>>>(
        gctx, gctx, gctx, wo, wo, wo, bo, bo, bo, out, out, out);
}

// round 11
// speedup vs baseline: 1.2300x; 1.0368x over previous
#include <cuda_runtime.h>
#include <cuda_fp16.h>
#include <math.h>
#include <stdint.h>

#define BB 2
#define SS 2048
#define DD 1024
#define HH 16
#define MM (BB*SS)

// Scratch (allocation-free rule: __device__ globals)
__device__ float g_Q[(size_t)MM * DD];
__device__ float g_K[(size_t)MM * DD];
__device__ float g_V[(size_t)MM * DD];
__device__ float g_ctx[(size_t)MM * DD];

__device__ __forceinline__ uint32_t f2tf(float f) {
    uint32_t u; asm("cvt.rna.tf32.f32 %0, %1;" : "=r"(u) : "f"(f)); return u;
}
__device__ __forceinline__ void mma8(float* d, const uint32_t* a, const uint32_t* b) {
    asm volatile(
        "mma.sync.aligned.m16n8k8.row.col.f32.tf32.tf32.f32 "
        "{%0,%1,%2,%3}, {%4,%5,%6,%7}, {%8,%9}, {%0,%1,%2,%3};\n"
        : "+f"(d[0]), "+f"(d[1]), "+f"(d[2]), "+f"(d[3])
        : "r"(a[0]), "r"(a[1]), "r"(a[2]), "r"(a[3]), "r"(b[0]), "r"(b[1]));
}
// fp16 MMA: D(16x8,f32) += A(16x16,f16) @ B(16x8,f16)
__device__ __forceinline__ void mma16(float* d, const uint32_t* a, const uint32_t* b) {
    asm volatile(
        "mma.sync.aligned.m16n8k16.row.col.f32.f16.f16.f32 "
        "{%0,%1,%2,%3}, {%4,%5,%6,%7}, {%8,%9}, {%0,%1,%2,%3};\n"
        : "+f"(d[0]), "+f"(d[1]), "+f"(d[2]), "+f"(d[3])
        : "r"(a[0]), "r"(a[1]), "r"(a[2]), "r"(a[3]), "r"(b[0]), "r"(b[1]));
}
__device__ __forceinline__ uint32_t f22h(float lo, float hi) {
    __half2 h = __floats2half2_rn(lo, hi);   // .x = lo (low 16 bits)
    return *(uint32_t*)&h;
}

// ===========================================================================
// GEMM: C = A @ W + bias (tf32 mma.sync).  Proven version (183us QKV).
// Block 128x128, BK=32, 256 threads = 8 warps as 2(M) x 4(N).
// Ping-pong SMEM, store-side convert, register prefetch, 1 barrier/chunk.
// ===========================================================================
#define GPA 36
#define GPB 136
#define GA_SZ (128 * GPA)
#define GB_SZ (32 * GPB)
#define GEMM_SMEM ((2 * GA_SZ + 2 * GB_SZ) * 4)   // 71680 B

__global__ void __launch_bounds__(256) gemm_tc(
    const float* __restrict__ A0, const float* __restrict__ A1, const float* __restrict__ A2,
    const float* __restrict__ W0, const float* __restrict__ W1, const float* __restrict__ W2,
    const float* __restrict__ b0, const float* __restrict__ b1, const float* __restrict__ b2,
    float* __restrict__ C0, float* __restrict__ C1, float* __restrict__ C2)
{
    extern __shared__ uint32_t gsm[];
    const int z = blockIdx.z;
    const float* A = (z == 0) ? A0 : (z == 1) ? A1 : A2;
    const float* W = (z == 0) ? W0 : (z == 1) ? W1 : W2;
    const float* bias = (z == 0) ? b0 : (z == 1) ? b1 : b2;
    float* C = (z == 0) ? C0 : (z == 1) ? C1 : C2;

    const int tid  = threadIdx.x;
    const int lane = tid & 31, warp = tid >> 5;
    const int g = lane >> 2, tig = lane & 3;
    const int wm = warp >> 2, wn = warp & 3;
    const int row0 = blockIdx.y * 128, col0 = blockIdx.x * 128;

    const int rA = tid >> 3, cA = (tid & 7) * 4;
    const int rB = tid >> 5, cB = (tid & 31) * 4;
    const float* Ap = A + (size_t)(row0 + rA) * DD + cA;
    const float* Wp = W + (size_t)rB * DD + col0 + cB;

    float acc[4][4][4] = {};
    float4 av[4], wv[4];

    #pragma unroll
    for (int i = 0; i < 4; i++) av[i] = *(const float4*)(Ap + (size_t)(32 * i) * DD);
    #pragma unroll
    for (int i = 0; i < 4; i++) wv[i] = *(const float4*)(Wp + (size_t)(8 * i) * DD);
    {
        uint32_t* As = gsm;
        uint32_t* Bs = gsm + 2 * GA_SZ;
        #pragma unroll
        for (int i = 0; i < 4; i++)
            *(uint4*)&As[(rA + 32 * i) * GPA + cA] =
                make_uint4(f2tf(av[i].x), f2tf(av[i].y), f2tf(av[i].z), f2tf(av[i].w));
        #pragma unroll
        for (int i = 0; i < 4; i++)
            *(uint4*)&Bs[(rB + 8 * i) * GPB + cB] =
                make_uint4(f2tf(wv[i].x), f2tf(wv[i].y), f2tf(wv[i].z), f2tf(wv[i].w));
    }
    __syncthreads();

    for (int c = 0; c < 32; c++) {
        if (c + 1 < 32) {
            const int k0 = (c + 1) * 32;
            #pragma unroll
            for (int i = 0; i < 4; i++)
                av[i] = *(const float4*)(Ap + k0 + (size_t)(32 * i) * DD);
            #pragma unroll
            for (int i = 0; i < 4; i++)
                wv[i] = *(const float4*)(Wp + (size_t)(k0 + 8 * i) * DD);
        }

        const uint32_t* As = gsm + (c & 1) * GA_SZ;
        const uint32_t* Bs = gsm + 2 * GA_SZ + (c & 1) * GB_SZ;

        #pragma unroll
        for (int kk = 0; kk < 4; kk++) {
            const int kb = kk * 8;
            uint32_t af[4][4], bf[4][2];
            #pragma unroll
            for (int mt = 0; mt < 4; mt++) {
                const int r = wm * 64 + mt * 16 + g;
                af[mt][0] = As[r * GPA + kb + tig];
                af[mt][1] = As[(r + 8) * GPA + kb + tig];
                af[mt][2] = As[r * GPA + kb + tig + 4];
                af[mt][3] = As[(r + 8) * GPA + kb + tig + 4];
            }
            #pragma unroll
            for (int j = 0; j < 4; j++) {
                const int n = wn * 32 + j * 8 + g;
                bf[j][0] = Bs[(kb + tig) * GPB + n];
                bf[j][1] = Bs[(kb + tig + 4) * GPB + n];
            }
            #pragma unroll
            for (int mt = 0; mt < 4; mt++)
                #pragma unroll
                for (int j = 0; j < 4; j++)
                    mma8(acc[mt][j], af[mt], bf[j]);
        }

        if (c + 1 < 32) {
            uint32_t* Asn = gsm + ((c + 1) & 1) * GA_SZ;
            uint32_t* Bsn = gsm + 2 * GA_SZ + ((c + 1) & 1) * GB_SZ;
            #pragma unroll
            for (int i = 0; i < 4; i++)
                *(uint4*)&Asn[(rA + 32 * i) * GPA + cA] =
                    make_uint4(f2tf(av[i].x), f2tf(av[i].y), f2tf(av[i].z), f2tf(av[i].w));
            #pragma unroll
            for (int i = 0; i < 4; i++)
                *(uint4*)&Bsn[(rB + 8 * i) * GPB + cB] =
                    make_uint4(f2tf(wv[i].x), f2tf(wv[i].y), f2tf(wv[i].z), f2tf(wv[i].w));
            __syncthreads();
        }
    }

    #pragma unroll
    for (int mt = 0; mt < 4; mt++) {
        #pragma unroll
        for (int j = 0; j < 4; j++) {
            const int n = col0 + wn * 32 + j * 8 + 2 * tig;
            const float bb0 = bias[n], bb1 = bias[n + 1];
            const int r = row0 + wm * 64 + mt * 16 + g;
            *(float2*)&C[(size_t)r * DD + n] =
                make_float2(acc[mt][j][0] + bb0, acc[mt][j][1] + bb1);
            *(float2*)&C[(size_t)(r + 8) * DD + n] =
                make_float2(acc[mt][j][2] + bb0, acc[mt][j][3] + bb1);
        }
    }
}

// ===========================================================================
// Flash attention, fp16 mma.sync m16n8k16, fp32 accumulate.
// CTA = (128-row q-tile, b, h). 128 threads = 4 warps x 32 q-rows (2 m-tiles).
// P stays in registers (C-frag of S == A-frag of PV for k16). K smem [key][dk]
// fp16 (row stride 36 words); V smem TRANSPOSED [dk][key] fp16 (stride 36).
// Double-buffered; LDGs for next tile issued before PV, converted+stored
// after PV; ONE __syncthreads per key-tile.
// SMEM: 2 stages x (K 2304 + Vt 2304 words) = 36864 B. Q staged in stage 1.
// ===========================================================================
#define RW 36                       // row stride in 4B words (72 halves)
#define KWD (64 * RW)               // 2304 words per K tile
#define VOFF KWD                    // Vt offset within a stage
#define STG (2 * KWD)               // 4608 words per stage
#define ATTN_SMEM (2 * STG * 4)     // 36864 B
#define NT (SS / 64)

__global__ void __launch_bounds__(128) attn_tc()
{
    extern __shared__ uint32_t sm[];

    const int tid  = threadIdx.x;
    const int lane = tid & 31, warp = tid >> 5;
    const int g = lane >> 2, tig = lane & 3;
    const int wr0 = warp * 32;
    const int qt = blockIdx.x;
    const int b  = blockIdx.y >> 4;
    const int h  = blockIdx.y & 15;

    const float* Qg = g_Q + (size_t)(b * SS + qt * 128) * DD + h * 64;
    const float* Kg = g_K + (size_t)(b * SS) * DD + h * 64;
    const float* Vg = g_V + (size_t)(b * SS) * DD + h * 64;

    // ---- prologue: stage Q (scaled, fp16) into stage-1 region ----
    #pragma unroll
    for (int p = 0; p < 16; p++) {
        const int i = tid + 128 * p;
        const int r = i >> 4, c4 = (i & 15) * 4;
        float4 qv = *(const float4*)(Qg + (size_t)r * DD + c4);
        *(uint2*)&sm[STG + r * RW + c4 / 2] =
            make_uint2(f22h(qv.x * 0.125f, qv.y * 0.125f),
                       f22h(qv.z * 0.125f, qv.w * 0.125f));
    }
    __syncthreads();

    // ---- extract persistent Q A-fragments (fp16 packed) ----
    uint32_t qa[2][4][4];
    #pragma unroll
    for (int mt = 0; mt < 2; mt++) {
        const int r = wr0 + mt * 16 + g;
        #pragma unroll
        for (int k16 = 0; k16 < 4; k16++) {
            const int base = STG + r * RW + k16 * 8 + tig;
            qa[mt][k16][0] = sm[base];
            qa[mt][k16][1] = sm[base + 8 * RW];
            qa[mt][k16][2] = sm[base + 4];
            qa[mt][k16][3] = sm[base + 8 * RW + 4];
        }
    }

    // ---- fill tile 0 into stage 0 (synchronous) ----
    {
        const float* Kt = Kg;
        const float* Vt = Vg;
        const int key = tid >> 1, dk0 = (tid & 1) * 32;
        #pragma unroll
        for (int i = 0; i < 8; i++) {
            float4 kf = *(const float4*)(Kt + (size_t)key * DD + dk0 + 4 * i);
            *(uint2*)&sm[key * RW + dk0 / 2 + 2 * i] =
                make_uint2(f22h(kf.x, kf.y), f22h(kf.z, kf.w));
        }
        const int pk = lane;
        #pragma unroll
        for (int p = 0; p < 4; p++) {
            const int d0 = (warp + 4 * p) * 4;
            float4 va = *(const float4*)(Vt + (size_t)(2 * pk) * DD + d0);
            float4 vb = *(const float4*)(Vt + (size_t)(2 * pk + 1) * DD + d0);
            const float* fa = (const float*)&va;
            const float* fb = (const float*)&vb;
            #pragma unroll
            for (int e = 0; e < 4; e++)
                sm[VOFF + (d0 + e) * RW + pk] = f22h(fa[e], fb[e]);
        }
    }
    __syncthreads();

    float of[2][8][4] = {};
    float mrow[2][2] = {{-1e30f, -1e30f}, {-1e30f, -1e30f}};
    float lrow[2][2] = {{0.f, 0.f}, {0.f, 0.f}};

    const int fkey = tid >> 1, fdk0 = (tid & 1) * 32;   // K-fill mapping
    const int fpk = lane;                                // V-fill mapping

    for (int kt = 0; kt < NT; kt++) {
        const uint32_t* Ks  = sm + (kt & 1) * STG;
        const uint32_t* Vts = sm + (kt & 1) * STG + VOFF;

        // ---- S = Qs @ K^T (fp16, k16 steps) ----
        float sf[2][8][4] = {};
        #pragma unroll
        for (int k16 = 0; k16 < 4; k16++) {
            uint32_t bf[8][2];
            #pragma unroll
            for (int j = 0; j < 8; j++) {
                const int w0 = (8 * j + g) * RW + 8 * k16 + tig;
                bf[j][0] = Ks[w0];
                bf[j][1] = Ks[w0 + 4];
            }
            #pragma unroll
            for (int mt = 0; mt < 2; mt++)
                #pragma unroll
                for (int j = 0; j < 8; j++)
                    mma16(sf[mt][j], qa[mt][k16], bf[j]);
        }

        // ---- online softmax ----
        #pragma unroll
        for (int mt = 0; mt < 2; mt++) {
            #pragma unroll
            for (int i = 0; i < 2; i++) {
                float mx = -1e30f;
                #pragma unroll
                for (int j = 0; j < 8; j++)
                    mx = fmaxf(mx, fmaxf(sf[mt][j][2 * i], sf[mt][j][2 * i + 1]));
                mx = fmaxf(mx, __shfl_xor_sync(0xffffffffu, mx, 1));
                mx = fmaxf(mx, __shfl_xor_sync(0xffffffffu, mx, 2));
                const float mn = fmaxf(mrow[mt][i], mx);
                const float corr = __expf(mrow[mt][i] - mn);
                mrow[mt][i] = mn;
                float rs = 0.f;
                #pragma unroll
                for (int j = 0; j < 8; j++) {
                    sf[mt][j][2 * i]     = __expf(sf[mt][j][2 * i] - mn);
                    sf[mt][j][2 * i + 1] = __expf(sf[mt][j][2 * i + 1] - mn);
                    rs += sf[mt][j][2 * i] + sf[mt][j][2 * i + 1];
                }
                rs += __shfl_xor_sync(0xffffffffu, rs, 1);
                rs += __shfl_xor_sync(0xffffffffu, rs, 2);
                lrow[mt][i] = lrow[mt][i] * corr + rs;
                #pragma unroll
                for (int j = 0; j < 8; j++) {
                    of[mt][j][2 * i]     *= corr;
                    of[mt][j][2 * i + 1] *= corr;
                }
            }
        }

        // ---- pack P into PV A-fragments (registers only; no SMEM) ----
        uint32_t pa[2][4][4];
        #pragma unroll
        for (int mt = 0; mt < 2; mt++)
            #pragma unroll
            for (int k16 = 0; k16 < 4; k16++) {
                pa[mt][k16][0] = f22h(sf[mt][2 * k16][0],     sf[mt][2 * k16][1]);
                pa[mt][k16][1] = f22h(sf[mt][2 * k16][2],     sf[mt][2 * k16][3]);
                pa[mt][k16][2] = f22h(sf[mt][2 * k16 + 1][0], sf[mt][2 * k16 + 1][1]);
                pa[mt][k16][3] = f22h(sf[mt][2 * k16 + 1][2], sf[mt][2 * k16 + 1][3]);
            }

        // ---- issue next tile's global loads (hide under PV) ----
        const bool more = (kt + 1 < NT);
        float4 kf[8], va[4], vb[4];
        if (more) {
            const float* Kt = Kg + (size_t)((kt + 1) * 64) * DD;
            const float* Vt = Vg + (size_t)((kt + 1) * 64) * DD;
            #pragma unroll
            for (int i = 0; i < 8; i++)
                kf[i] = *(const float4*)(Kt + (size_t)fkey * DD + fdk0 + 4 * i);
            #pragma unroll
            for (int p = 0; p < 4; p++) {
                const int d0 = (warp + 4 * p) * 4;
                va[p] = *(const float4*)(Vt + (size_t)(2 * fpk) * DD + d0);
                vb[p] = *(const float4*)(Vt + (size_t)(2 * fpk + 1) * DD + d0);
            }
        }

        // ---- O += P @ V (B-frags from transposed V) ----
        #pragma unroll
        for (int k16 = 0; k16 < 4; k16++) {
            uint32_t bb[8][2];
            #pragma unroll
            for (int j = 0; j < 8; j++) {
                const int w0 = (8 * j + g) * RW + 8 * k16 + tig;
                bb[j][0] = Vts[w0];
                bb[j][1] = Vts[w0 + 4];
            }
            #pragma unroll
            for (int mt = 0; mt < 2; mt++)
                #pragma unroll
                for (int j = 0; j < 8; j++)
                    mma16(of[mt][j], pa[mt][k16], bb[j]);
        }

        // ---- convert + store next tile, single barrier ----
        if (more) {
            uint32_t* dst = sm + ((kt + 1) & 1) * STG;
            #pragma unroll
            for (int i = 0; i < 8; i++)
                *(uint2*)&dst[fkey * RW + fdk0 / 2 + 2 * i] =
                    make_uint2(f22h(kf[i].x, kf[i].y), f22h(kf[i].z, kf[i].w));
            #pragma unroll
            for (int p = 0; p < 4; p++) {
                const int d0 = (warp + 4 * p) * 4;
                const float* fa = (const float*)&va[p];
                const float* fb = (const float*)&vb[p];
                #pragma unroll
                for (int e = 0; e < 4; e++)
                    dst[VOFF + (d0 + e) * RW + fpk] = f22h(fa[e], fb[e]);
            }
        }
        __syncthreads();
    }

    // ---- normalize + write context ----
    #pragma unroll
    for (int mt = 0; mt < 2; mt++) {
        const float inv0 = 1.f / lrow[mt][0], inv1 = 1.f / lrow[mt][1];
        const size_t orow = (size_t)(b * SS + qt * 128 + wr0 + mt * 16 + g);
        #pragma unroll
        for (int j = 0; j < 8; j++) {
            const int n = h * 64 + j * 8 + 2 * tig;
            *(float2*)&g_ctx[orow * DD + n] =
                make_float2(of[mt][j][0] * inv0, of[mt][j][1] * inv0);
            *(float2*)&g_ctx[(orow + 8) * DD + n] =
                make_float2(of[mt][j][2] * inv1, of[mt][j][3] * inv1);
        }
    }
}

// ---------------------------------------------------------------------------
extern "C" void kernel_launch(void* const* d_in, const int* in_sizes, int n_in,
                              void* d_out, int out_size)
{
    (void)in_sizes; (void)n_in; (void)out_size;
    const float* q  = (const float*)d_in[0];
    const float* k  = (const float*)d_in[1];
    const float* v  = (const float*)d_in[2];
    const float* wq = (const float*)d_in[3];
    const float* bq = (const float*)d_in[4];
    const float* wk = (const float*)d_in[5];
    const float* bk = (const float*)d_in[6];
    const float* wv = (const float*)d_in[7];
    const float* bv = (const float*)d_in[8];
    const float* wo = (const float*)d_in[9];
    const float* bo = (const float*)d_in[10];
    float* out = (float*)d_out;

    float *gq, *gk, *gv, *gctx;
    cudaGetSymbolAddress((void**)&gq,   g_Q);
    cudaGetSymbolAddress((void**)&gk,   g_K);
    cudaGetSymbolAddress((void**)&gv,   g_V);
    cudaGetSymbolAddress((void**)&gctx, g_ctx);

    cudaFuncSetAttribute(gemm_tc, cudaFuncAttributeMaxDynamicSharedMemorySize, GEMM_SMEM);

    // fused Q/K/V projections: one launch, grid.z = 3
    gemm_tc<<<dim3(DD / 128, MM / 128, 3), 256, GEMM_SMEM>>>(
        q, k, v, wq, wk, wv, bq, bk, bv, gq, gk, gv);

    attn_tc<<<dim3(SS / 128, BB * HH), 128, ATTN_SMEM>>>();

    // output projection
    gemm_tc<<<dim3(DD / 128, MM / 128, 1), 256, GEMM_SMEM>>>(
        gctx, gctx, gctx, wo, wo, wo, bo, bo, bo, out, out, out);
}